// round 13
// baseline (speedup 1.0000x reference)
#include <cuda_runtime.h>
#include <math.h>
#include <stdint.h>

#define NB 48
#define SS 1024
#define DD 128
#define DKK 64
#define WSTRIDE 136   // [k][n] W row stride in words: >=128 and ==8 (mod 32)

// scratch (static device globals: allocation-free per harness rules)
__device__ float g_Q[NB * SS * DKK];   // tf32-rounded projections
__device__ float g_K[NB * SS * DKK];
__device__ float g_Z[NB];
__device__ int   g_cnt[NB];

__device__ __forceinline__ uint32_t f2tf32(float v) {
    uint32_t r;
    asm("cvt.rna.tf32.f32 %0, %1;" : "=r"(r) : "f"(v));
    return r;
}

// ---------------------------------------------------------------------------
// Kernel 1: fused Q|K projection, 2-term tf32: C = Ah*Wh + Ah*Wl.
// (R12-exact: in-CTA W staging at stride 136, no setup kernel, outputs
// tf32-rounded; verified bit-identical rel_err.)
// ---------------------------------------------------------------------------
#define PROJ_SMEM (128 * 36 * 4 + 2 * 32 * WSTRIDE * 4)

__global__ __launch_bounds__(256) void proj_kernel(
    const float* __restrict__ A,
    const float* __restrict__ Wq,
    const float* __restrict__ Wk)
{
    if (blockIdx.x == 0 && threadIdx.x < NB) {
        g_Z[threadIdx.x] = 0.f;
        g_cnt[threadIdx.x] = 0;
    }

    extern __shared__ uint32_t smem[];
    uint32_t* sAh = smem;                  // [128][36]
    uint32_t* sWh = sAh + 128 * 36;        // [k][n], stride WSTRIDE
    uint32_t* sWl = sWh + 32 * WSTRIDE;

    const int tid  = threadIdx.x;
    const int lane = tid & 31, warp = tid >> 5;
    const int rowbase = blockIdx.x * 128;

    const int mrow = (warp & 3) * 32;
    const int ncol = (warp >> 2) * 64;
    const int g  = lane >> 2;
    const int tr = lane & 3;

    float acc[2][8][4];
#pragma unroll
    for (int mt = 0; mt < 2; mt++)
#pragma unroll
        for (int nt = 0; nt < 8; nt++)
#pragma unroll
            for (int r = 0; r < 4; r++) acc[mt][nt][r] = 0.f;

    for (int k0 = 0; k0 < DD; k0 += 32) {
#pragma unroll
        for (int it = 0; it < 4; it++) {
            int f = tid + 256 * it;
            int m = f >> 3, k4 = (f & 7) * 4;
            float4 v = *(const float4*)(A + (size_t)(rowbase + m) * DD + k0 + k4);
            uint4 h = make_uint4(f2tf32(v.x), f2tf32(v.y),
                                 f2tf32(v.z), f2tf32(v.w));
            *(uint4*)&sAh[m * 36 + k4] = h;
        }
#pragma unroll
        for (int it = 0; it < 4; it++) {
            int f4 = tid + 256 * it;
            int k  = f4 >> 5;
            int n4 = (f4 & 31) * 4;
            float4 v = (n4 < 64)
                ? *(const float4*)(Wq + (size_t)(k0 + k) * DKK + n4)
                : *(const float4*)(Wk + (size_t)(k0 + k) * DKK + (n4 - 64));
            uint4 h = make_uint4(f2tf32(v.x), f2tf32(v.y),
                                 f2tf32(v.z), f2tf32(v.w));
            uint4 l = make_uint4(
                f2tf32(v.x - __uint_as_float(h.x)),
                f2tf32(v.y - __uint_as_float(h.y)),
                f2tf32(v.z - __uint_as_float(h.z)),
                f2tf32(v.w - __uint_as_float(h.w)));
            *(uint4*)&sWh[k * WSTRIDE + n4] = h;
            *(uint4*)&sWl[k * WSTRIDE + n4] = l;
        }
        __syncthreads();

#pragma unroll
        for (int kc = 0; kc < 4; kc++) {
            const int kk = kc * 8;
            uint32_t ah[2][4];
#pragma unroll
            for (int mt = 0; mt < 2; mt++) {
                int r = mrow + mt * 16 + g;
                ah[mt][0] = sAh[r * 36 + kk + tr];
                ah[mt][1] = sAh[(r + 8) * 36 + kk + tr];
                ah[mt][2] = sAh[r * 36 + kk + tr + 4];
                ah[mt][3] = sAh[(r + 8) * 36 + kk + tr + 4];
            }
#pragma unroll
            for (int nt = 0; nt < 8; nt++) {
                int c = ncol + nt * 8 + g;
                uint32_t bh0 = sWh[(kk + tr) * WSTRIDE + c];
                uint32_t bh1 = sWh[(kk + tr + 4) * WSTRIDE + c];
                uint32_t bl0 = sWl[(kk + tr) * WSTRIDE + c];
                uint32_t bl1 = sWl[(kk + tr + 4) * WSTRIDE + c];
#pragma unroll
                for (int mt = 0; mt < 2; mt++) {
                    asm volatile(
                        "mma.sync.aligned.m16n8k8.row.col.f32.tf32.tf32.f32 "
                        "{%0,%1,%2,%3}, {%4,%5,%6,%7}, {%8,%9}, {%0,%1,%2,%3};"
                        : "+f"(acc[mt][nt][0]), "+f"(acc[mt][nt][1]),
                          "+f"(acc[mt][nt][2]), "+f"(acc[mt][nt][3])
                        : "r"(ah[mt][0]), "r"(ah[mt][1]), "r"(ah[mt][2]), "r"(ah[mt][3]),
                          "r"(bh0), "r"(bh1));
                    asm volatile(
                        "mma.sync.aligned.m16n8k8.row.col.f32.tf32.tf32.f32 "
                        "{%0,%1,%2,%3}, {%4,%5,%6,%7}, {%8,%9}, {%0,%1,%2,%3};"
                        : "+f"(acc[mt][nt][0]), "+f"(acc[mt][nt][1]),
                          "+f"(acc[mt][nt][2]), "+f"(acc[mt][nt][3])
                        : "r"(ah[mt][0]), "r"(ah[mt][1]), "r"(ah[mt][2]), "r"(ah[mt][3]),
                          "r"(bl0), "r"(bl1));
                }
            }
        }
        __syncthreads();
    }

#pragma unroll
    for (int mt = 0; mt < 2; mt++) {
        int m0 = rowbase + mrow + mt * 16 + g;
#pragma unroll
        for (int nt = 0; nt < 8; nt++) {
            int c = ncol + nt * 8 + tr * 2;
            float* dst = (c < 64) ? g_Q : g_K;
            int cc = c & 63;
            *(float2*)(dst + (size_t)m0 * DKK + cc) = make_float2(
                __uint_as_float(f2tf32(acc[mt][nt][0])),
                __uint_as_float(f2tf32(acc[mt][nt][1])));
            *(float2*)(dst + (size_t)(m0 + 8) * DKK + cc) = make_float2(
                __uint_as_float(f2tf32(acc[mt][nt][2])),
                __uint_as_float(f2tf32(acc[mt][nt][3])));
        }
    }
}

// ---------------------------------------------------------------------------
// Kernel 2: score tile 128x128, now with 512 THREADS (16 warps, 4x4 grid of
// 32x32 warp-tiles): per-thread acc drops 64->32 floats so natural regs
// (~55) fit the __launch_bounds__(512,2) 64-reg cap. 2 CTAs/SM x 16 warps =
// 32 warps/SM (occ 37%->50%) with identical memory traffic, MMA count, and
// per-element arithmetic (same k order) -> output bit-identical to R12.
// Self-normalizing Z protocol unchanged (64 CTAs per batch).
// ---------------------------------------------------------------------------
#define SCORE_SMEM (2 * 128 * 68 * 4)

__device__ __forceinline__ float uexp(float x) {
    float t, r, u;
    asm("ex2.approx.f32 %0, %1;" : "=f"(t) : "f"(x * 2.8853900817779268f));
    asm("rcp.approx.f32 %0, %1;" : "=f"(r) : "f"(t + 1.0f));
    asm("ex2.approx.f32 %0, %1;" : "=f"(u) : "f"(r * -28.853900817779268f));
    return u;
}

__global__ __launch_bounds__(512, 2) void score_kernel(float* __restrict__ out)
{
    extern __shared__ uint32_t ssm[];
    uint32_t* sQ = ssm;                // [128][68]
    uint32_t* sK = ssm + 128 * 68;
    __shared__ float swarp[16];
    __shared__ float sinv;

    const int tid  = threadIdx.x;
    const int lane = tid & 31, warp = tid >> 5;   // 16 warps
    const int bz    = blockIdx.x >> 6;
    const int tile  = blockIdx.x & 63;
    const int qbase = (tile >> 3) * 128;
    const int sbase = (tile & 7) * 128;

    const float* Qb = g_Q + (size_t)bz * SS * DKK + (size_t)qbase * DKK;
    const float* Kb = g_K + (size_t)bz * SS * DKK + (size_t)sbase * DKK;

    const int mrow = (warp & 3) * 32;     // 4 m-warps
    const int ncol = (warp >> 2) * 32;    // 4 n-warps
    const int g  = lane >> 2;
    const int tr = lane & 3;

    // stage full 128x64 Q and K tiles via cp.async (pure copy)
#pragma unroll
    for (int it = 0; it < 4; it++) {
        int f = tid + 512 * it;            // 0..2047
        int m = f >> 4, k4 = (f & 15) * 4;
        uint32_t dq = (uint32_t)__cvta_generic_to_shared(&sQ[m * 68 + k4]);
        asm volatile("cp.async.cg.shared.global [%0], [%1], 16;"
                     :: "r"(dq), "l"(Qb + m * DKK + k4));
        uint32_t dk = (uint32_t)__cvta_generic_to_shared(&sK[m * 68 + k4]);
        asm volatile("cp.async.cg.shared.global [%0], [%1], 16;"
                     :: "r"(dk), "l"(Kb + m * DKK + k4));
    }
    asm volatile("cp.async.commit_group;");

    float acc[2][4][4];
#pragma unroll
    for (int mt = 0; mt < 2; mt++)
#pragma unroll
        for (int nt = 0; nt < 4; nt++)
#pragma unroll
            for (int r = 0; r < 4; r++) acc[mt][nt][r] = 0.f;

    asm volatile("cp.async.wait_group 0;");
    __syncthreads();

#pragma unroll
    for (int kc = 0; kc < 8; kc++) {
        const int k0 = kc * 8;
        uint32_t a[2][4];
#pragma unroll
        for (int mt = 0; mt < 2; mt++) {
            int r = mrow + mt * 16 + g;
            a[mt][0] = sQ[r * 68 + k0 + tr];
            a[mt][1] = sQ[(r + 8) * 68 + k0 + tr];
            a[mt][2] = sQ[r * 68 + k0 + tr + 4];
            a[mt][3] = sQ[(r + 8) * 68 + k0 + tr + 4];
        }
#pragma unroll
        for (int nt = 0; nt < 4; nt++) {
            int c = ncol + nt * 8 + g;
            uint32_t b0 = sK[c * 68 + k0 + tr];
            uint32_t b1 = sK[c * 68 + k0 + tr + 4];
#pragma unroll
            for (int mt = 0; mt < 2; mt++) {
                asm volatile(
                    "mma.sync.aligned.m16n8k8.row.col.f32.tf32.tf32.f32 "
                    "{%0,%1,%2,%3}, {%4,%5,%6,%7}, {%8,%9}, {%0,%1,%2,%3};"
                    : "+f"(acc[mt][nt][0]), "+f"(acc[mt][nt][1]),
                      "+f"(acc[mt][nt][2]), "+f"(acc[mt][nt][3])
                    : "r"(a[mt][0]), "r"(a[mt][1]), "r"(a[mt][2]), "r"(a[mt][3]),
                      "r"(b0), "r"(b1));
            }
        }
    }

    // transform in place (u stays in registers), accumulate local sum.
    float local = 0.f;
    if (qbase == sbase) {
#pragma unroll
        for (int mt = 0; mt < 2; mt++) {
            int r0 = mrow + mt * 16 + g;
#pragma unroll
            for (int nt = 0; nt < 4; nt++) {
                int c = ncol + nt * 8 + tr * 2;
                float u0 = uexp(acc[mt][nt][0]); if (r0     == c    ) u0 = 0.f;
                float u1 = uexp(acc[mt][nt][1]); if (r0     == c + 1) u1 = 0.f;
                float u2 = uexp(acc[mt][nt][2]); if (r0 + 8 == c    ) u2 = 0.f;
                float u3 = uexp(acc[mt][nt][3]); if (r0 + 8 == c + 1) u3 = 0.f;
                acc[mt][nt][0] = u0; acc[mt][nt][1] = u1;
                acc[mt][nt][2] = u2; acc[mt][nt][3] = u3;
                local += (u0 + u1) + (u2 + u3);
            }
        }
    } else {
#pragma unroll
        for (int mt = 0; mt < 2; mt++)
#pragma unroll
            for (int nt = 0; nt < 4; nt++) {
                float u0 = uexp(acc[mt][nt][0]);
                float u1 = uexp(acc[mt][nt][1]);
                float u2 = uexp(acc[mt][nt][2]);
                float u3 = uexp(acc[mt][nt][3]);
                acc[mt][nt][0] = u0; acc[mt][nt][1] = u1;
                acc[mt][nt][2] = u2; acc[mt][nt][3] = u3;
                local += (u0 + u1) + (u2 + u3);
            }
    }
    // block reduce -> one atomicAdd + arrival count; spin until batch done
#pragma unroll
    for (int o = 16; o; o >>= 1)
        local += __shfl_down_sync(0xffffffffu, local, o);
    if (lane == 0) swarp[warp] = local;
    __syncthreads();
    if (tid == 0) {
        float tot = swarp[0];
#pragma unroll
        for (int w = 1; w < 16; w++) tot += swarp[w];
        atomicAdd(&g_Z[bz], tot);
        __threadfence();
        atomicAdd(&g_cnt[bz], 1);
        volatile int* vc = g_cnt;
        while (vc[bz] < 64) { }
        volatile float* vz = g_Z;
        sinv = 1.0f / vz[bz];
    }
    __syncthreads();
    const float inv = sinv;

    // single normalized write
    float* orow = out + ((size_t)bz << 20);
#pragma unroll
    for (int mt = 0; mt < 2; mt++) {
        int r0 = qbase + mrow + mt * 16 + g;
#pragma unroll
        for (int nt = 0; nt < 4; nt++) {
            int c = sbase + ncol + nt * 8 + tr * 2;
            *(float2*)(orow + (size_t)r0 * SS + c) =
                make_float2(acc[mt][nt][0] * inv, acc[mt][nt][1] * inv);
            *(float2*)(orow + (size_t)(r0 + 8) * SS + c) =
                make_float2(acc[mt][nt][2] * inv, acc[mt][nt][3] * inv);
        }
    }
}

// ---------------------------------------------------------------------------
extern "C" void kernel_launch(void* const* d_in, const int* in_sizes, int n_in,
                              void* d_out, int out_size)
{
    const float* q  = (const float*)d_in[0];   // query [48,1024,128]
    const float* wq = (const float*)d_in[3];   // W_query [128,64]
    const float* wk = (const float*)d_in[4];   // W_key   [128,64]
    float* out = (float*)d_out;                // [48, 1024*1024] fp32

    cudaFuncSetAttribute(proj_kernel,
                         cudaFuncAttributeMaxDynamicSharedMemorySize, PROJ_SMEM);
    cudaFuncSetAttribute(score_kernel,
                         cudaFuncAttributeMaxDynamicSharedMemorySize, SCORE_SMEM);

    proj_kernel<<<384, 256, PROJ_SMEM>>>(q, wq, wk);
    score_kernel<<<3072, 512, SCORE_SMEM>>>(out);
}

// round 14
// speedup vs baseline: 1.0124x; 1.0124x over previous
#include <cuda_runtime.h>
#include <math.h>
#include <stdint.h>

#define NB 48
#define SS 1024
#define DD 128
#define DKK 64

// scratch (static device globals: allocation-free per harness rules)
__device__ float g_Q[NB * SS * DKK];   // tf32-rounded projections
__device__ float g_K[NB * SS * DKK];
__device__ float g_Z[NB];
__device__ int   g_cnt[NB];
// W split into tf32 hi/lo, TRANSPOSED to [n][k] (n: 0..63 Wq, 64..127 Wk)
__device__ uint32_t g_WhT[DD * DD];
__device__ uint32_t g_WlT[DD * DD];

__device__ __forceinline__ uint32_t f2tf32(float v) {
    uint32_t r;
    asm("cvt.rna.tf32.f32 %0, %1;" : "=r"(r) : "f"(v));
    return r;
}

// ---------------------------------------------------------------------------
// Kernel 0: split W into tf32 hi/lo and transpose to [n][k]; zero g_Z/g_cnt.
// ---------------------------------------------------------------------------
__global__ __launch_bounds__(256) void setup_kernel(
    const float* __restrict__ Wq, const float* __restrict__ Wk)
{
    int idx = blockIdx.x * 256 + threadIdx.x;   // grid 64 -> 16384
    int k = idx >> 7, n = idx & 127;
    float v = (n < 64) ? Wq[k * DKK + n] : Wk[k * DKK + (n - 64)];
    uint32_t hi = f2tf32(v);
    uint32_t lo = f2tf32(v - __uint_as_float(hi));
    g_WhT[n * DD + k] = hi;
    g_WlT[n * DD + k] = lo;
    if (idx < NB) { g_Z[idx] = 0.f; g_cnt[idx] = 0; }
}

// ---------------------------------------------------------------------------
// Kernel 1: fused Q|K projection, 2-term tf32: C = Ah*Wh + Ah*Wl.
// (R9 structure.) W tables staged via cp.async PURE COPY (already tf32),
// issued BEFORE the A cvt/STS work so the W flight time hides behind it.
// Outputs tf32-rounded so score stages them as a raw cp.async copy.
// ---------------------------------------------------------------------------
#define PROJ_SMEM (3 * 128 * 36 * 4)

__global__ __launch_bounds__(256) void proj_kernel(const float* __restrict__ A)
{
    extern __shared__ uint32_t smem[];
    uint32_t* sAh = smem;                 // [128][36]
    uint32_t* sWh = sAh + 128 * 36;       // [n][k] transposed, stride 36
    uint32_t* sWl = sWh + 128 * 36;

    const int tid  = threadIdx.x;
    const int lane = tid & 31, warp = tid >> 5;
    const int rowbase = blockIdx.x * 128;

    const int mrow = (warp & 3) * 32;
    const int ncol = (warp >> 2) * 64;
    const int g  = lane >> 2;
    const int tr = lane & 3;

    float acc[2][8][4];
#pragma unroll
    for (int mt = 0; mt < 2; mt++)
#pragma unroll
        for (int nt = 0; nt < 8; nt++)
#pragma unroll
            for (int r = 0; r < 4; r++) acc[mt][nt][r] = 0.f;

    for (int k0 = 0; k0 < DD; k0 += 32) {
        // issue W table copies first (pure cp.async, rows 16B-aligned: 144B)
#pragma unroll
        for (int it = 0; it < 4; it++) {
            int f = tid + 256 * it;
            int n = f >> 3, k4 = (f & 7) * 4;
            uint32_t dh = (uint32_t)__cvta_generic_to_shared(&sWh[n * 36 + k4]);
            asm volatile("cp.async.cg.shared.global [%0], [%1], 16;"
                         :: "r"(dh), "l"(g_WhT + n * DD + k0 + k4));
            uint32_t dl = (uint32_t)__cvta_generic_to_shared(&sWl[n * 36 + k4]);
            asm volatile("cp.async.cg.shared.global [%0], [%1], 16;"
                         :: "r"(dl), "l"(g_WlT + n * DD + k0 + k4));
        }
        asm volatile("cp.async.commit_group;");

        // stage A chunk 128x32 (cvt to tf32 through regs, STS.128)
#pragma unroll
        for (int it = 0; it < 4; it++) {
            int f = tid + 256 * it;
            int m = f >> 3, k4 = (f & 7) * 4;
            float4 v = *(const float4*)(A + (size_t)(rowbase + m) * DD + k0 + k4);
            uint4 h = make_uint4(f2tf32(v.x), f2tf32(v.y),
                                 f2tf32(v.z), f2tf32(v.w));
            *(uint4*)&sAh[m * 36 + k4] = h;
        }
        asm volatile("cp.async.wait_group 0;");
        __syncthreads();

#pragma unroll
        for (int kc = 0; kc < 4; kc++) {
            const int kk = kc * 8;
            uint32_t ah[2][4];
#pragma unroll
            for (int mt = 0; mt < 2; mt++) {
                int r = mrow + mt * 16 + g;
                ah[mt][0] = sAh[r * 36 + kk + tr];
                ah[mt][1] = sAh[(r + 8) * 36 + kk + tr];
                ah[mt][2] = sAh[r * 36 + kk + tr + 4];
                ah[mt][3] = sAh[(r + 8) * 36 + kk + tr + 4];
            }
#pragma unroll
            for (int nt = 0; nt < 8; nt++) {
                int c = ncol + nt * 8 + g;
                uint32_t bh0 = sWh[c * 36 + kk + tr];
                uint32_t bh1 = sWh[c * 36 + kk + tr + 4];
                uint32_t bl0 = sWl[c * 36 + kk + tr];
                uint32_t bl1 = sWl[c * 36 + kk + tr + 4];
#pragma unroll
                for (int mt = 0; mt < 2; mt++) {
                    asm volatile(
                        "mma.sync.aligned.m16n8k8.row.col.f32.tf32.tf32.f32 "
                        "{%0,%1,%2,%3}, {%4,%5,%6,%7}, {%8,%9}, {%0,%1,%2,%3};"
                        : "+f"(acc[mt][nt][0]), "+f"(acc[mt][nt][1]),
                          "+f"(acc[mt][nt][2]), "+f"(acc[mt][nt][3])
                        : "r"(ah[mt][0]), "r"(ah[mt][1]), "r"(ah[mt][2]), "r"(ah[mt][3]),
                          "r"(bh0), "r"(bh1));
                    asm volatile(
                        "mma.sync.aligned.m16n8k8.row.col.f32.tf32.tf32.f32 "
                        "{%0,%1,%2,%3}, {%4,%5,%6,%7}, {%8,%9}, {%0,%1,%2,%3};"
                        : "+f"(acc[mt][nt][0]), "+f"(acc[mt][nt][1]),
                          "+f"(acc[mt][nt][2]), "+f"(acc[mt][nt][3])
                        : "r"(ah[mt][0]), "r"(ah[mt][1]), "r"(ah[mt][2]), "r"(ah[mt][3]),
                          "r"(bl0), "r"(bl1));
                }
            }
        }
        __syncthreads();
    }

    // store tf32-ROUNDED outputs (score stages them as a raw copy)
#pragma unroll
    for (int mt = 0; mt < 2; mt++) {
        int m0 = rowbase + mrow + mt * 16 + g;
#pragma unroll
        for (int nt = 0; nt < 8; nt++) {
            int c = ncol + nt * 8 + tr * 2;
            float* dst = (c < 64) ? g_Q : g_K;
            int cc = c & 63;
            *(float2*)(dst + (size_t)m0 * DKK + cc) = make_float2(
                __uint_as_float(f2tf32(acc[mt][nt][0])),
                __uint_as_float(f2tf32(acc[mt][nt][1])));
            *(float2*)(dst + (size_t)(m0 + 8) * DKK + cc) = make_float2(
                __uint_as_float(f2tf32(acc[mt][nt][2])),
                __uint_as_float(f2tf32(acc[mt][nt][3])));
        }
    }
}

// ---------------------------------------------------------------------------
// Kernel 2: score tile + self-normalizing epilogue (R9-exact arithmetic,
// 256 threads). Staging now SPLIT into two cp.async groups by k-halves:
// wait_group 1 releases the first half -> MMA kc 0-3 overlaps the in-flight
// second half -> wait_group 0 -> kc 4-7. Same values, same order.
// ---------------------------------------------------------------------------
#define SCORE_SMEM (2 * 128 * 68 * 4)

__device__ __forceinline__ float uexp(float x) {
    float t, r, u;
    asm("ex2.approx.f32 %0, %1;" : "=f"(t) : "f"(x * 2.8853900817779268f));
    asm("rcp.approx.f32 %0, %1;" : "=f"(r) : "f"(t + 1.0f));
    asm("ex2.approx.f32 %0, %1;" : "=f"(u) : "f"(r * -28.853900817779268f));
    return u;
}

__global__ __launch_bounds__(256, 3) void score_kernel(float* __restrict__ out)
{
    extern __shared__ uint32_t ssm[];
    uint32_t* sQ = ssm;                // [128][68]
    uint32_t* sK = ssm + 128 * 68;
    __shared__ float swarp[8];
    __shared__ float sinv;

    const int tid  = threadIdx.x;
    const int lane = tid & 31, warp = tid >> 5;
    const int bz    = blockIdx.x >> 6;
    const int tile  = blockIdx.x & 63;
    const int qbase = (tile >> 3) * 128;
    const int sbase = (tile & 7) * 128;

    const float* Qb = g_Q + (size_t)bz * SS * DKK + (size_t)qbase * DKK;
    const float* Kb = g_K + (size_t)bz * SS * DKK + (size_t)sbase * DKK;

    const int mrow = (warp & 3) * 32;
    const int ncol = (warp >> 2) * 64;
    const int g  = lane >> 2;
    const int tr = lane & 3;

    // group A: k-words [0,32) of Q and K
#pragma unroll
    for (int it = 0; it < 4; it++) {
        int f = tid + 256 * it;            // 0..1023
        int m = f >> 3, k4 = (f & 7) * 4;  // words 0..28
        uint32_t dq = (uint32_t)__cvta_generic_to_shared(&sQ[m * 68 + k4]);
        asm volatile("cp.async.cg.shared.global [%0], [%1], 16;"
                     :: "r"(dq), "l"(Qb + m * DKK + k4));
        uint32_t dk = (uint32_t)__cvta_generic_to_shared(&sK[m * 68 + k4]);
        asm volatile("cp.async.cg.shared.global [%0], [%1], 16;"
                     :: "r"(dk), "l"(Kb + m * DKK + k4));
    }
    asm volatile("cp.async.commit_group;");
    // group B: k-words [32,64)
#pragma unroll
    for (int it = 0; it < 4; it++) {
        int f = tid + 256 * it;
        int m = f >> 3, k4 = (f & 7) * 4 + 32;
        uint32_t dq = (uint32_t)__cvta_generic_to_shared(&sQ[m * 68 + k4]);
        asm volatile("cp.async.cg.shared.global [%0], [%1], 16;"
                     :: "r"(dq), "l"(Qb + m * DKK + k4));
        uint32_t dk = (uint32_t)__cvta_generic_to_shared(&sK[m * 68 + k4]);
        asm volatile("cp.async.cg.shared.global [%0], [%1], 16;"
                     :: "r"(dk), "l"(Kb + m * DKK + k4));
    }
    asm volatile("cp.async.commit_group;");

    float acc[2][8][4];
#pragma unroll
    for (int mt = 0; mt < 2; mt++)
#pragma unroll
        for (int nt = 0; nt < 8; nt++)
#pragma unroll
            for (int r = 0; r < 4; r++) acc[mt][nt][r] = 0.f;

    // first k-half ready -> MMA kc 0-3 while second half is in flight
    asm volatile("cp.async.wait_group 1;");
    __syncthreads();

#pragma unroll
    for (int kc = 0; kc < 4; kc++) {
        const int k0 = kc * 8;
        uint32_t a[2][4];
#pragma unroll
        for (int mt = 0; mt < 2; mt++) {
            int r = mrow + mt * 16 + g;
            a[mt][0] = sQ[r * 68 + k0 + tr];
            a[mt][1] = sQ[(r + 8) * 68 + k0 + tr];
            a[mt][2] = sQ[r * 68 + k0 + tr + 4];
            a[mt][3] = sQ[(r + 8) * 68 + k0 + tr + 4];
        }
#pragma unroll
        for (int nt = 0; nt < 8; nt++) {
            int c = ncol + nt * 8 + g;
            uint32_t b0 = sK[c * 68 + k0 + tr];
            uint32_t b1 = sK[c * 68 + k0 + tr + 4];
#pragma unroll
            for (int mt = 0; mt < 2; mt++) {
                asm volatile(
                    "mma.sync.aligned.m16n8k8.row.col.f32.tf32.tf32.f32 "
                    "{%0,%1,%2,%3}, {%4,%5,%6,%7}, {%8,%9}, {%0,%1,%2,%3};"
                    : "+f"(acc[mt][nt][0]), "+f"(acc[mt][nt][1]),
                      "+f"(acc[mt][nt][2]), "+f"(acc[mt][nt][3])
                    : "r"(a[mt][0]), "r"(a[mt][1]), "r"(a[mt][2]), "r"(a[mt][3]),
                      "r"(b0), "r"(b1));
            }
        }
    }

    asm volatile("cp.async.wait_group 0;");
    __syncthreads();

#pragma unroll
    for (int kc = 4; kc < 8; kc++) {
        const int k0 = kc * 8;
        uint32_t a[2][4];
#pragma unroll
        for (int mt = 0; mt < 2; mt++) {
            int r = mrow + mt * 16 + g;
            a[mt][0] = sQ[r * 68 + k0 + tr];
            a[mt][1] = sQ[(r + 8) * 68 + k0 + tr];
            a[mt][2] = sQ[r * 68 + k0 + tr + 4];
            a[mt][3] = sQ[(r + 8) * 68 + k0 + tr + 4];
        }
#pragma unroll
        for (int nt = 0; nt < 8; nt++) {
            int c = ncol + nt * 8 + g;
            uint32_t b0 = sK[c * 68 + k0 + tr];
            uint32_t b1 = sK[c * 68 + k0 + tr + 4];
#pragma unroll
            for (int mt = 0; mt < 2; mt++) {
                asm volatile(
                    "mma.sync.aligned.m16n8k8.row.col.f32.tf32.tf32.f32 "
                    "{%0,%1,%2,%3}, {%4,%5,%6,%7}, {%8,%9}, {%0,%1,%2,%3};"
                    : "+f"(acc[mt][nt][0]), "+f"(acc[mt][nt][1]),
                      "+f"(acc[mt][nt][2]), "+f"(acc[mt][nt][3])
                    : "r"(a[mt][0]), "r"(a[mt][1]), "r"(a[mt][2]), "r"(a[mt][3]),
                      "r"(b0), "r"(b1));
            }
        }
    }

    // transform in place (u stays in registers), accumulate local sum.
    // Diagonal tiles (8/64) take the q==s select; others skip it entirely.
    float local = 0.f;
    if (qbase == sbase) {
#pragma unroll
        for (int mt = 0; mt < 2; mt++) {
            int r0 = mrow + mt * 16 + g;
#pragma unroll
            for (int nt = 0; nt < 8; nt++) {
                int c = ncol + nt * 8 + tr * 2;
                float u0 = uexp(acc[mt][nt][0]); if (r0     == c    ) u0 = 0.f;
                float u1 = uexp(acc[mt][nt][1]); if (r0     == c + 1) u1 = 0.f;
                float u2 = uexp(acc[mt][nt][2]); if (r0 + 8 == c    ) u2 = 0.f;
                float u3 = uexp(acc[mt][nt][3]); if (r0 + 8 == c + 1) u3 = 0.f;
                acc[mt][nt][0] = u0; acc[mt][nt][1] = u1;
                acc[mt][nt][2] = u2; acc[mt][nt][3] = u3;
                local += (u0 + u1) + (u2 + u3);
            }
        }
    } else {
#pragma unroll
        for (int mt = 0; mt < 2; mt++)
#pragma unroll
            for (int nt = 0; nt < 8; nt++) {
                float u0 = uexp(acc[mt][nt][0]);
                float u1 = uexp(acc[mt][nt][1]);
                float u2 = uexp(acc[mt][nt][2]);
                float u3 = uexp(acc[mt][nt][3]);
                acc[mt][nt][0] = u0; acc[mt][nt][1] = u1;
                acc[mt][nt][2] = u2; acc[mt][nt][3] = u3;
                local += (u0 + u1) + (u2 + u3);
            }
    }
    // block reduce -> one atomicAdd + arrival count; spin until batch done
#pragma unroll
    for (int o = 16; o; o >>= 1)
        local += __shfl_down_sync(0xffffffffu, local, o);
    if (lane == 0) swarp[warp] = local;
    __syncthreads();
    if (tid == 0) {
        float tot = swarp[0];
#pragma unroll
        for (int w = 1; w < 8; w++) tot += swarp[w];
        atomicAdd(&g_Z[bz], tot);
        __threadfence();
        atomicAdd(&g_cnt[bz], 1);
        volatile int* vc = g_cnt;
        while (vc[bz] < 64) { }
        volatile float* vz = g_Z;
        sinv = 1.0f / vz[bz];
    }
    __syncthreads();
    const float inv = sinv;

    // single normalized write
    float* orow = out + ((size_t)bz << 20);
#pragma unroll
    for (int mt = 0; mt < 2; mt++) {
        int r0 = qbase + mrow + mt * 16 + g;
#pragma unroll
        for (int nt = 0; nt < 8; nt++) {
            int c = sbase + ncol + nt * 8 + tr * 2;
            *(float2*)(orow + (size_t)r0 * SS + c) =
                make_float2(acc[mt][nt][0] * inv, acc[mt][nt][1] * inv);
            *(float2*)(orow + (size_t)(r0 + 8) * SS + c) =
                make_float2(acc[mt][nt][2] * inv, acc[mt][nt][3] * inv);
        }
    }
}

// ---------------------------------------------------------------------------
extern "C" void kernel_launch(void* const* d_in, const int* in_sizes, int n_in,
                              void* d_out, int out_size)
{
    const float* q  = (const float*)d_in[0];   // query [48,1024,128]
    const float* wq = (const float*)d_in[3];   // W_query [128,64]
    const float* wk = (const float*)d_in[4];   // W_key   [128,64]
    float* out = (float*)d_out;                // [48, 1024*1024] fp32

    cudaFuncSetAttribute(proj_kernel,
                         cudaFuncAttributeMaxDynamicSharedMemorySize, PROJ_SMEM);
    cudaFuncSetAttribute(score_kernel,
                         cudaFuncAttributeMaxDynamicSharedMemorySize, SCORE_SMEM);

    setup_kernel<<<64, 256>>>(wq, wk);
    proj_kernel<<<384, 256, PROJ_SMEM>>>(q);
    score_kernel<<<3072, 256, SCORE_SMEM>>>(out);
}